// round 6
// baseline (speedup 1.0000x reference)
#include <cuda_runtime.h>

// filtfilt (butter(4,0.2)) over (8,64,48000) fp32 — fused smem kernel, v5.
// vs v4: packed f32x2 processing. Each thread runs the IIR on TWO rows at
// once (rows 2r and 2r+1 interleaved as 64-bit pairs in smem), using PTX
// fma.rn.f32x2 (sm_10x FFMA2 — ptxas never auto-fuses this). Per 2 samples:
// 1 LDS.64 + 9 FFMA2 + 1 STS.64, i.e. per-sample issue is halved vs v4.
// NSEG=8, L=25 (odd -> conflict-free 64-bit banks), W=48 warmup
// (max |pole| = 0.7956 -> 0.7956^48 = 1.7e-5 << 1e-3 threshold).

#define T_LEN  48000
#define PADL   15
#define TP     (T_LEN + 2 * PADL)   // 48030
#define ROWS   512
#define NSEG   8
#define SEGC   6004                 // 8*6004 = 48032 >= TP
#define NTHR   256
#define L      25                   // chunk per thread (odd)
#define W      48                   // warmup
#define HALO   52                   // seam halo (W + 4 taps)
#define BODY   (NTHR * L)           // 6400 >= SEGC + 2*HALO = 6108
#define SMEMN  (W + BODY + W)       // 6496 pairs
#define SMEMB  (SMEMN * 8)          // 51968 B -> 4 blocks/SM

#define B0c 0.004824343357716228f
#define B1c 0.019297373430864913f
#define B2c 0.02894606014629737f
#define B3c 0.019297373430864913f
#define B4c 0.004824343357716228f
#define A1c (-2.369513007182038f)
#define A2c ( 2.3139884144006455f)
#define A3c (-1.0546654058785672f)
#define A4c ( 0.18737949236818502f)

typedef unsigned long long u64;

__device__ __forceinline__ u64 pk2(float c) {            // broadcast c to both lanes
    unsigned int u = __float_as_uint(c);
    return ((u64)u << 32) | u;
}
__device__ __forceinline__ u64 pk2f(float lo, float hi) {
    return ((u64)__float_as_uint(hi) << 32) | __float_as_uint(lo);
}

#define MUL2(d, a, b) \
    asm("mul.rn.f32x2 %0, %1, %2;" : "=l"(d) : "l"(a), "l"(b))
#define FMA2(d, a, b, c) \
    asm("fma.rn.f32x2 %0, %1, %2, %3;" : "=l"(d) : "l"(a), "l"(b), "l"(c))

// Packed IIR step on two independent streams. The loop-carried dependency
// through s1_ is the LAST fma (4-cycle recurrence per 2 samples).
#define IIR_STEP(xn, yout)                               \
    do {                                                 \
        u64 f_;                                          \
        MUL2(f_, cB0, (xn));                             \
        FMA2(f_, cB1, w0_, f_);                          \
        FMA2(f_, cB2, w1_, f_);                          \
        FMA2(f_, cB3, w2_, f_);                          \
        FMA2(f_, cB4, w3_, f_);                          \
        FMA2(f_, cA2, s2_, f_);                          \
        FMA2(f_, cA3, s3_, f_);                          \
        FMA2(f_, cA4, s4_, f_);                          \
        FMA2((yout), cA1, s1_, f_);                      \
        w3_ = w2_; w2_ = w1_; w1_ = w0_; w0_ = (xn);     \
        s4_ = s3_; s3_ = s2_; s2_ = s1_; s1_ = (yout);   \
    } while (0)

#define IIR_RESET() \
    u64 w0_ = 0, w1_ = 0, w2_ = 0, w3_ = 0, \
        s1_ = 0, s2_ = 0, s3_ = 0, s4_ = 0

// Odd-pad reflected load from one row at raw index j (padded coord - PADL).
__device__ __forceinline__ float load_refl(const float* __restrict__ xr, int j) {
    if (j < 0)      return 2.f * xr[0]         - xr[-1 - j];
    if (j >= T_LEN) return 2.f * xr[T_LEN - 1] - xr[2 * T_LEN - 3 - j];
    return xr[j];
}

__global__ void __launch_bounds__(NTHR, 4)
fused_filtfilt2(const float* __restrict__ x, float* __restrict__ out) {
    extern __shared__ u64 smem2[];
    u64* xsp = smem2 + W;                    // body coord 0
    const int tid = threadIdx.x;
    const int blk = blockIdx.x;
    const int rp = blk >> 3;                 // row pair index (0..255)
    const int sg = blk & 7;
    const float* __restrict__ xr0 = x + (size_t)(2 * rp) * T_LEN;
    const float* __restrict__ xr1 = xr0 + T_LEN;
    float* __restrict__ or0 = out + (size_t)(2 * rp) * T_LEN;
    float* __restrict__ or1 = or0 + T_LEN;

    const int core0 = sg * SEGC;
    const int core1 = min(core0 + SEGC, TP);
    const int e0 = max(0, core0 - HALO);     // padded coord of body[0]
    const int ext_end = min(TP, core1 + HALO);
    const int ext_len = ext_end - e0;

    // Packed coefficients (registers; f32x2 has no imm form)
    const u64 cB0 = pk2(B0c), cB1 = pk2(B1c), cB2 = pk2(B2c),
              cB3 = pk2(B3c), cB4 = pk2(B4c);
    const u64 cA1 = pk2(-A1c), cA2 = pk2(-A2c), cA3 = pk2(-A3c), cA4 = pk2(-A4c);

    // ---- Load both rows (coalesced) into interleaved pairs + zero aprons ----
    if (sg == 0 || sg == NSEG - 1) {
        for (int i = tid; i < SMEMN; i += NTHR) {
            int bi = i - W;
            u64 v = 0;
            if (bi >= 0 && bi < ext_len) {
                int j = e0 + bi - PADL;
                v = pk2f(load_refl(xr0, j), load_refl(xr1, j));
            }
            smem2[i] = v;
        }
    } else {
        const float* s0 = xr0 + (e0 - PADL);
        const float* s1 = xr1 + (e0 - PADL);
        for (int i = tid; i < SMEMN; i += NTHR) {
            int bi = i - W;
            smem2[i] = (bi >= 0 && bi < ext_len)
                           ? pk2f(__ldg(s0 + bi), __ldg(s1 + bi)) : 0ULL;
        }
    }
    __syncthreads();

    const int ps = tid * L;

    // ---- Forward pass (in place) ----
    {
        IIR_RESET();
        u64 y;
#pragma unroll 4
        for (int s = 0; s < W; ++s) {
            u64 xn = xsp[ps - W + s];
            IIR_STEP(xn, y);
        }
        __syncthreads();                     // cross-chunk reads before writes
#pragma unroll 5
        for (int s = 0; s < L; ++s) {
            int t = ps + s;
            u64 xn = xsp[t];
            IIR_STEP(xn, y);
            xsp[t] = y;
        }
    }
    __syncthreads();

    // ---- Re-zero beyond valid extent (exact zero-init at padded row end) ----
    for (int i = ext_len + tid; i < BODY; i += NTHR) xsp[i] = 0ULL;
    __syncthreads();

    // ---- Backward pass (in place, reversed) ----
    {
        IIR_RESET();
        u64 y;
        const int tb = ps + L - 1 + W;
#pragma unroll 4
        for (int s = 0; s < W; ++s) {
            u64 yn = xsp[tb - s];
            IIR_STEP(yn, y);
        }
        __syncthreads();
#pragma unroll 5
        for (int s = 0; s < L; ++s) {
            int t = ps + L - 1 - s;
            u64 yn = xsp[t];
            IIR_STEP(yn, y);
            xsp[t] = y;
        }
    }
    __syncthreads();

    // ---- Store core ∩ [PADL, TP-PADL): unpack pair -> both rows ----
    const int wlo = max(core0, PADL);
    const int whi = min(core1, TP - PADL);
    for (int p = wlo + tid; p < whi; p += NTHR) {
        u64 v = xsp[p - e0];
        or0[p - PADL] = __uint_as_float((unsigned int)v);
        or1[p - PADL] = __uint_as_float((unsigned int)(v >> 32));
    }
}

extern "C" void kernel_launch(void* const* d_in, const int* in_sizes, int n_in,
                              void* d_out, int out_size) {
    const float* x = (const float*)d_in[0];
    float* out = (float*)d_out;
    cudaFuncSetAttribute(fused_filtfilt2,
                         cudaFuncAttributeMaxDynamicSharedMemorySize, SMEMB);
    fused_filtfilt2<<<(ROWS / 2) * NSEG, NTHR, SMEMB>>>(x, out);
}

// round 7
// speedup vs baseline: 1.5448x; 1.5448x over previous
#include <cuda_runtime.h>

// filtfilt (butter(4,0.2)) over (8,64,48000) fp32 — fused smem kernel, v6.
// v4 architecture (scalar FFMA with immediate coefficients: rt_SMSP=1), with:
//  - NSEG=8, L=25 -> smem 25.9KB -> 8 blocks/SM = 64 warps (100% occ cap)
//  - W=40 warmup (0.7956^40 = 1.1e-4; measured err tracks ~3x below bound)
//  - fully unrolled 25-step chunk loops (immediate LDS/STS offsets, no IADD)

#define T_LEN  48000
#define PADL   15
#define TP     (T_LEN + 2 * PADL)   // 48030
#define ROWS   512
#define NSEG   8
#define SEGC   6004                 // 8*6004 = 48032 >= TP
#define NTHR   256
#define L      25                   // chunk per thread (odd -> conflict-free)
#define W      40                   // warmup
#define HALO   44                   // seam halo (W + taps)
#define BODY   (NTHR * L)           // 6400 >= SEGC + 2*HALO = 6092
#define SMEMN  (W + BODY + W)       // 6480 floats
#define SMEMB  (SMEMN * 4)          // 25920 B -> 8 blocks/SM

#define B0c 0.004824343357716228f
#define B1c 0.019297373430864913f
#define B2c 0.02894606014629737f
#define B3c 0.019297373430864913f
#define B4c 0.004824343357716228f
#define A1c (-2.369513007182038f)
#define A2c ( 2.3139884144006455f)
#define A3c (-1.0546654058785672f)
#define A4c ( 0.18737949236818502f)

// One IIR step; constant multipliers -> FFMA-imm (rt_SMSP=1). Loop-carried
// dependency through s1_ is the LAST fma (4-cycle recurrence).
#define IIR_STEP(xn, yout)                                   \
    do {                                                     \
        float f_ = B0c * (xn);                               \
        f_ = fmaf(B1c, w0_, f_);                             \
        f_ = fmaf(B2c, w1_, f_);                             \
        f_ = fmaf(B3c, w2_, f_);                             \
        f_ = fmaf(B4c, w3_, f_);                             \
        f_ = fmaf(-A2c, s2_, f_);                            \
        f_ = fmaf(-A3c, s3_, f_);                            \
        f_ = fmaf(-A4c, s4_, f_);                            \
        (yout) = fmaf(-A1c, s1_, f_);                        \
        w3_ = w2_; w2_ = w1_; w1_ = w0_; w0_ = (xn);         \
        s4_ = s3_; s3_ = s2_; s2_ = s1_; s1_ = (yout);       \
    } while (0)

#define IIR_RESET() \
    float w0_ = 0.f, w1_ = 0.f, w2_ = 0.f, w3_ = 0.f, \
          s1_ = 0.f, s2_ = 0.f, s3_ = 0.f, s4_ = 0.f

__global__ void __launch_bounds__(NTHR, 8)
fused_filtfilt(const float* __restrict__ x, float* __restrict__ out) {
    extern __shared__ float smem_raw[];
    float* xsp = smem_raw + W;               // body coord 0
    const int tid = threadIdx.x;
    const int blk = blockIdx.x;
    const int r = blk >> 3;
    const int sg = blk & 7;
    const float* __restrict__ xr = x + (size_t)r * T_LEN;
    float* __restrict__ outr = out + (size_t)r * T_LEN;

    const int core0 = sg * SEGC;
    const int core1 = min(core0 + SEGC, TP);
    const int e0 = max(0, core0 - HALO);     // padded coord of body[0]
    const int ext_end = min(TP, core1 + HALO);
    const int ext_len = ext_end - e0;

    // ---- Load (coalesced) + zero aprons; odd-pad reflection at row edges ----
    if (sg == 0 || sg == NSEG - 1) {
        for (int i = tid; i < SMEMN; i += NTHR) {
            int bi = i - W;
            float v = 0.f;
            if (bi >= 0 && bi < ext_len) {
                int j = e0 + bi - PADL;
                if (j < 0)           v = 2.f * xr[0]         - xr[-1 - j];
                else if (j >= T_LEN) v = 2.f * xr[T_LEN - 1] - xr[2 * T_LEN - 3 - j];
                else                 v = xr[j];
            }
            smem_raw[i] = v;
        }
    } else {                                  // interior: no reflection possible
        const float* src = xr + (e0 - PADL);
        for (int i = tid; i < SMEMN; i += NTHR) {
            int bi = i - W;
            smem_raw[i] = (bi >= 0 && bi < ext_len) ? __ldg(src + bi) : 0.f;
        }
    }
    __syncthreads();

    const int ps = tid * L;

    // ---- Forward pass (in place) ----
    {
        IIR_RESET();
        float y;
        const float* wp = xsp + ps - W;
#pragma unroll 8
        for (int s = 0; s < W; ++s) {
            float xn = wp[s];
            IIR_STEP(xn, y);
        }
        __syncthreads();                      // cross-chunk reads before writes
        float* cp = xsp + ps;
#pragma unroll
        for (int s = 0; s < L; ++s) {         // full unroll: immediate offsets
            float xn = cp[s];
            IIR_STEP(xn, y);
            cp[s] = y;
        }
    }
    __syncthreads();

    // ---- Re-zero beyond valid extent: backward recursion at the padded row
    //      end must start from exact zeros (reference zero-init semantics). ----
    for (int i = ext_len + tid; i < BODY; i += NTHR) xsp[i] = 0.f;
    __syncthreads();

    // ---- Backward pass (in place, reversed) ----
    {
        IIR_RESET();
        float y;
        const float* wp = xsp + ps + L - 1 + W;
#pragma unroll 8
        for (int s = 0; s < W; ++s) {
            float yn = wp[-s];
            IIR_STEP(yn, y);
        }
        __syncthreads();
        float* cp = xsp + ps + L - 1;
#pragma unroll
        for (int s = 0; s < L; ++s) {         // full unroll: immediate offsets
            float yn = cp[-s];
            IIR_STEP(yn, y);
            cp[-s] = y;
        }
    }
    __syncthreads();

    // ---- Store core ∩ [PADL, TP-PADL) (coalesced) ----
    const int wlo = max(core0, PADL);
    const int whi = min(core1, TP - PADL);
    for (int p = wlo + tid; p < whi; p += NTHR) {
        outr[p - PADL] = xsp[p - e0];
    }
}

extern "C" void kernel_launch(void* const* d_in, const int* in_sizes, int n_in,
                              void* d_out, int out_size) {
    const float* x = (const float*)d_in[0];
    float* out = (float*)d_out;
    cudaFuncSetAttribute(fused_filtfilt,
                         cudaFuncAttributeMaxDynamicSharedMemorySize, SMEMB);
    fused_filtfilt<<<ROWS * NSEG, NTHR, SMEMB>>>(x, out);
}

// round 9
// speedup vs baseline: 1.7192x; 1.1129x over previous
#include <cuda_runtime.h>

// filtfilt (butter(4,0.2)) over (8,64,48000) fp32 — fused smem kernel, v7b.
// vs v6 (81us): the per-chunk warmup no longer runs the serial IIR. The
// zero-state warmup output equals a truncated-FIR convolution with the
// impulse response h[k], so the 4 needed states y[t0-1..t0-4] are built as
// 4 shared-load dot products: W x (1 LDS + 4 FFMA-imm) instead of
// W x (1 LDS + 9 serial FFMA). Warmup was ~51% of issued instructions.
// v7b fix: constexpr h-table lives at FUNCTION scope (device-usable without
// --expt-relaxed-constexpr); full unroll folds every h[k] to an immediate.

#define T_LEN  48000
#define PADL   15
#define TP     (T_LEN + 2 * PADL)   // 48030
#define ROWS   512
#define NSEG   8
#define SEGC   6004                 // 8*6004 = 48032 >= TP
#define NTHR   256
#define L      25                   // chunk per thread (odd -> conflict-free)
#define W      40                   // warmup depth (FIR truncation)
#define HALO   44                   // seam halo
#define BODY   (NTHR * L)           // 6400 >= SEGC + 2*HALO = 6092
#define SMEMN  (W + BODY + W)       // 6480 floats
#define SMEMB  (SMEMN * 4)          // 25920 B -> 8 blocks/SM

#define B0c 0.004824343357716228f
#define B1c 0.019297373430864913f
#define B2c 0.02894606014629737f
#define B3c 0.019297373430864913f
#define B4c 0.004824343357716228f
#define A1c (-2.369513007182038f)
#define A2c ( 2.3139884144006455f)
#define A3c (-1.0546654058785672f)
#define A4c ( 0.18737949236818502f)

// Impulse response h[k] of the IIR, computed at compile time.
struct HArr { float h[W]; };
__host__ __device__ constexpr HArr make_h() {
    HArr r{};
    double hd[W] = {};
    const double b[5] = {0.004824343357716228, 0.019297373430864913,
                         0.02894606014629737, 0.019297373430864913,
                         0.004824343357716228};
    const double a[4] = {-2.369513007182038, 2.3139884144006455,
                         -1.0546654058785672, 0.18737949236818502};
    for (int k = 0; k < W; ++k) {
        double v = (k < 5) ? b[k] : 0.0;
        for (int j = 0; j < 4; ++j)
            if (k - 1 - j >= 0) v -= a[j] * hd[k - 1 - j];
        hd[k] = v;
        r.h[k] = (float)v;
    }
    return r;
}

// One IIR step; constant multipliers -> FFMA-imm (rt_SMSP=1). Loop-carried
// dependency through s1_ is the LAST fma (4-cycle recurrence).
#define IIR_STEP(xn, yout)                                   \
    do {                                                     \
        float f_ = B0c * (xn);                               \
        f_ = fmaf(B1c, w0_, f_);                             \
        f_ = fmaf(B2c, w1_, f_);                             \
        f_ = fmaf(B3c, w2_, f_);                             \
        f_ = fmaf(B4c, w3_, f_);                             \
        f_ = fmaf(-A2c, s2_, f_);                            \
        f_ = fmaf(-A3c, s3_, f_);                            \
        f_ = fmaf(-A4c, s4_, f_);                            \
        (yout) = fmaf(-A1c, s1_, f_);                        \
        w3_ = w2_; w2_ = w1_; w1_ = w0_; w0_ = (xn);         \
        s4_ = s3_; s3_ = s2_; s2_ = s1_; s1_ = (yout);       \
    } while (0)

// FIR warmup: p points at the sample just BEFORE the chunk (in processing
// order); p[DIR*i] walks further back. Produces the 4 IIR states
// (s1_=y[-1]..s4_=y[-4]) and the 4-tap input window (w0_=x[-1]..w3_=x[-4]).
// HCk is a function-local constexpr -> every h index folds to an immediate.
#define FIR_WARMUP(p, DIR)                                   \
    constexpr HArr HCk = make_h();                           \
    float w0_ = 0.f, w1_ = 0.f, w2_ = 0.f, w3_ = 0.f,        \
          s1_ = 0.f, s2_ = 0.f, s3_ = 0.f, s4_ = 0.f;        \
    _Pragma("unroll")                                        \
    for (int i_ = 0; i_ < W; ++i_) {                         \
        float v_ = (p)[(DIR) * i_];                          \
        if (i_ == 0) w0_ = v_;                               \
        else if (i_ == 1) w1_ = v_;                          \
        else if (i_ == 2) w2_ = v_;                          \
        else if (i_ == 3) w3_ = v_;                          \
        s1_ = fmaf(HCk.h[i_], v_, s1_);                      \
        if (i_ >= 1) s2_ = fmaf(HCk.h[i_ - 1], v_, s2_);     \
        if (i_ >= 2) s3_ = fmaf(HCk.h[i_ - 2], v_, s3_);     \
        if (i_ >= 3) s4_ = fmaf(HCk.h[i_ - 3], v_, s4_);     \
    }

__global__ void __launch_bounds__(NTHR, 8)
fused_filtfilt(const float* __restrict__ x, float* __restrict__ out) {
    extern __shared__ float smem_raw[];
    float* xsp = smem_raw + W;               // body coord 0
    const int tid = threadIdx.x;
    const int blk = blockIdx.x;
    const int r = blk >> 3;
    const int sg = blk & 7;
    const float* __restrict__ xr = x + (size_t)r * T_LEN;
    float* __restrict__ outr = out + (size_t)r * T_LEN;

    const int core0 = sg * SEGC;
    const int core1 = min(core0 + SEGC, TP);
    const int e0 = max(0, core0 - HALO);     // padded coord of body[0]
    const int ext_end = min(TP, core1 + HALO);
    const int ext_len = ext_end - e0;

    // ---- Load (coalesced) + zero aprons; odd-pad reflection at row edges ----
    if (sg == 0 || sg == NSEG - 1) {
        for (int i = tid; i < SMEMN; i += NTHR) {
            int bi = i - W;
            float v = 0.f;
            if (bi >= 0 && bi < ext_len) {
                int j = e0 + bi - PADL;
                if (j < 0)           v = 2.f * xr[0]         - xr[-1 - j];
                else if (j >= T_LEN) v = 2.f * xr[T_LEN - 1] - xr[2 * T_LEN - 3 - j];
                else                 v = xr[j];
            }
            smem_raw[i] = v;
        }
    } else {                                  // interior: no reflection possible
        const float* src = xr + (e0 - PADL);
        for (int i = tid; i < SMEMN; i += NTHR) {
            int bi = i - W;
            smem_raw[i] = (bi >= 0 && bi < ext_len) ? __ldg(src + bi) : 0.f;
        }
    }
    __syncthreads();

    const int ps = tid * L;

    // ---- Forward pass (in place) ----
    {
        FIR_WARMUP(xsp + ps - 1, -1);         // states from preceding W samples
        float y;
        __syncthreads();                      // cross-chunk reads before writes
        float* cp = xsp + ps;
#pragma unroll
        for (int s = 0; s < L; ++s) {         // full unroll: immediate offsets
            float xn = cp[s];
            IIR_STEP(xn, y);
            cp[s] = y;
        }
    }
    __syncthreads();

    // ---- Re-zero beyond valid extent: backward recursion at the padded row
    //      end must start from exact zeros (reference zero-init semantics). ----
    for (int i = ext_len + tid; i < BODY; i += NTHR) xsp[i] = 0.f;
    __syncthreads();

    // ---- Backward pass (in place, reversed) ----
    {
        FIR_WARMUP(xsp + ps + L, +1);         // states from following W samples
        float y;
        __syncthreads();
        float* cp = xsp + ps + L - 1;
#pragma unroll
        for (int s = 0; s < L; ++s) {         // full unroll: immediate offsets
            float yn = cp[-s];
            IIR_STEP(yn, y);
            cp[-s] = y;
        }
    }
    __syncthreads();

    // ---- Store core ∩ [PADL, TP-PADL) (coalesced) ----
    const int wlo = max(core0, PADL);
    const int whi = min(core1, TP - PADL);
    for (int p = wlo + tid; p < whi; p += NTHR) {
        outr[p - PADL] = xsp[p - e0];
    }
}

extern "C" void kernel_launch(void* const* d_in, const int* in_sizes, int n_in,
                              void* d_out, int out_size) {
    const float* x = (const float*)d_in[0];
    float* out = (float*)d_out;
    cudaFuncSetAttribute(fused_filtfilt,
                         cudaFuncAttributeMaxDynamicSharedMemorySize, SMEMB);
    fused_filtfilt<<<ROWS * NSEG, NTHR, SMEMB>>>(x, out);
}

// round 10
// speedup vs baseline: 1.7337x; 1.0084x over previous
#include <cuda_runtime.h>

// filtfilt (butter(4,0.2)) over (8,64,48000) fp32 — fused smem kernel, v8.
// vs v7b (72.8us): all hot-loop shared accesses are 64-bit (float2).
// L=26 (even -> 8B-aligned chunk starts; stride-26 v2 accesses provably
// bank-conflict-free), NSEG=8, smem 26.9KB -> still 8 blocks/SM.
// Warmup: 20 LDS.64 + 160 FFMA-imm. Chunk: 13 LDS.64 + 13 STS.64 + 234 FFMA.
// ~25% fewer issued warp-instructions than v7b (LSU count was co-limiter).

#define T_LEN  48000
#define PADL   15
#define TP     (T_LEN + 2 * PADL)   // 48030
#define ROWS   512
#define NSEG   8
#define SEGC   6004                 // 8*6004 = 48032 >= TP
#define NTHR   256
#define L      26                   // chunk per thread (even, conflict-free v2)
#define W      40                   // warmup depth (FIR truncation)
#define HALO   44                   // seam halo
#define BODY   (NTHR * L)           // 6656 >= SEGC + 2*HALO = 6092
#define SMEMN  (W + BODY + W)       // 6736 floats
#define SMEMB  (SMEMN * 4)          // 26944 B -> 8 blocks/SM (with 1KB reserve)

#define B0c 0.004824343357716228f
#define B1c 0.019297373430864913f
#define B2c 0.02894606014629737f
#define B3c 0.019297373430864913f
#define B4c 0.004824343357716228f
#define A1c (-2.369513007182038f)
#define A2c ( 2.3139884144006455f)
#define A3c (-1.0546654058785672f)
#define A4c ( 0.18737949236818502f)

// Impulse response h[k] of the IIR, computed at compile time.
struct HArr { float h[W]; };
__host__ __device__ constexpr HArr make_h() {
    HArr r{};
    double hd[W] = {};
    const double b[5] = {0.004824343357716228, 0.019297373430864913,
                         0.02894606014629737, 0.019297373430864913,
                         0.004824343357716228};
    const double a[4] = {-2.369513007182038, 2.3139884144006455,
                         -1.0546654058785672, 0.18737949236818502};
    for (int k = 0; k < W; ++k) {
        double v = (k < 5) ? b[k] : 0.0;
        for (int j = 0; j < 4; ++j)
            if (k - 1 - j >= 0) v -= a[j] * hd[k - 1 - j];
        hd[k] = v;
        r.h[k] = (float)v;
    }
    return r;
}

struct St { float w0, w1, w2, w3, s1, s2, s3, s4; };

// Truncated-FIR warmup over the W samples in [base, base+W) (8B-aligned).
// REV=false: forward pass (window precedes chunk; i = W-1-j back-distance).
// REV=true : backward pass (window follows chunk; i = j back-distance).
// Full unroll folds every h index to an immediate -> FFMA-imm form.
template <bool REV>
__device__ __forceinline__ St fir_warmup(const float* base) {
    constexpr HArr HCk = make_h();
    const float2* p2 = reinterpret_cast<const float2*>(base);
    St st = {0.f, 0.f, 0.f, 0.f, 0.f, 0.f, 0.f, 0.f};
#pragma unroll
    for (int q = 0; q < W / 2; ++q) {
        float2 v = p2[q];
#pragma unroll
        for (int e = 0; e < 2; ++e) {
            const int j = 2 * q + e;
            const int i = REV ? j : (W - 1 - j);
            const float val = e ? v.y : v.x;
            st.s1 = fmaf(HCk.h[i], val, st.s1);
            if (i >= 1) st.s2 = fmaf(HCk.h[i - 1], val, st.s2);
            if (i >= 2) st.s3 = fmaf(HCk.h[i - 2], val, st.s3);
            if (i >= 3) st.s4 = fmaf(HCk.h[i - 3], val, st.s4);
            if (i == 0) st.w0 = val;
            if (i == 1) st.w1 = val;
            if (i == 2) st.w2 = val;
            if (i == 3) st.w3 = val;
        }
    }
    return st;
}

// One IIR step; constant multipliers -> FFMA-imm (rt_SMSP=1). Loop-carried
// dependency through s1_ is the LAST fma (4-cycle recurrence).
#define IIR_STEP(xn, yout)                                   \
    do {                                                     \
        float f_ = B0c * (xn);                               \
        f_ = fmaf(B1c, w0_, f_);                             \
        f_ = fmaf(B2c, w1_, f_);                             \
        f_ = fmaf(B3c, w2_, f_);                             \
        f_ = fmaf(B4c, w3_, f_);                             \
        f_ = fmaf(-A2c, s2_, f_);                            \
        f_ = fmaf(-A3c, s3_, f_);                            \
        f_ = fmaf(-A4c, s4_, f_);                            \
        (yout) = fmaf(-A1c, s1_, f_);                        \
        w3_ = w2_; w2_ = w1_; w1_ = w0_; w0_ = (xn);         \
        s4_ = s3_; s3_ = s2_; s2_ = s1_; s1_ = (yout);       \
    } while (0)

#define ST_UNPACK(st)                                        \
    float w0_ = st.w0, w1_ = st.w1, w2_ = st.w2, w3_ = st.w3, \
          s1_ = st.s1, s2_ = st.s2, s3_ = st.s3, s4_ = st.s4

__global__ void __launch_bounds__(NTHR, 8)
fused_filtfilt(const float* __restrict__ x, float* __restrict__ out) {
    extern __shared__ float smem_raw[];
    float* xsp = smem_raw + W;               // body coord 0 (8B-aligned: W=40)
    const int tid = threadIdx.x;
    const int blk = blockIdx.x;
    const int r = blk >> 3;
    const int sg = blk & 7;
    const float* __restrict__ xr = x + (size_t)r * T_LEN;
    float* __restrict__ outr = out + (size_t)r * T_LEN;

    const int core0 = sg * SEGC;
    const int core1 = min(core0 + SEGC, TP);
    const int e0 = max(0, core0 - HALO);     // padded coord of body[0]
    const int ext_end = min(TP, core1 + HALO);
    const int ext_len = ext_end - e0;

    // ---- Load (coalesced) + zero aprons; odd-pad reflection at row edges ----
    if (sg == 0 || sg == NSEG - 1) {
        for (int i = tid; i < SMEMN; i += NTHR) {
            int bi = i - W;
            float v = 0.f;
            if (bi >= 0 && bi < ext_len) {
                int j = e0 + bi - PADL;
                if (j < 0)           v = 2.f * xr[0]         - xr[-1 - j];
                else if (j >= T_LEN) v = 2.f * xr[T_LEN - 1] - xr[2 * T_LEN - 3 - j];
                else                 v = xr[j];
            }
            smem_raw[i] = v;
        }
    } else {                                  // interior: no reflection possible
        const float* src = xr + (e0 - PADL);
        for (int i = tid; i < SMEMN; i += NTHR) {
            int bi = i - W;
            smem_raw[i] = (bi >= 0 && bi < ext_len) ? __ldg(src + bi) : 0.f;
        }
    }
    __syncthreads();

    const int ps = tid * L;                   // 26*tid: 8B-aligned word index

    // ---- Forward pass (in place, float2) ----
    {
        St st = fir_warmup<false>(xsp + ps - W);
        ST_UNPACK(st);
        __syncthreads();                      // cross-chunk reads before writes
        float2* cp2 = reinterpret_cast<float2*>(xsp + ps);
        float y0, y1;
#pragma unroll
        for (int q = 0; q < L / 2; ++q) {
            float2 v = cp2[q];
            IIR_STEP(v.x, y0);
            IIR_STEP(v.y, y1);
            cp2[q] = make_float2(y0, y1);
        }
    }
    __syncthreads();

    // ---- Re-zero beyond valid extent: backward recursion at the padded row
    //      end must start from exact zeros (reference zero-init semantics). ----
    for (int i = ext_len + tid; i < BODY; i += NTHR) xsp[i] = 0.f;
    __syncthreads();

    // ---- Backward pass (in place, reversed, float2) ----
    {
        St st = fir_warmup<true>(xsp + ps + L);
        ST_UNPACK(st);
        __syncthreads();
        float2* cp2 = reinterpret_cast<float2*>(xsp + ps);
        float y0, y1;
#pragma unroll
        for (int q = L / 2 - 1; q >= 0; --q) {
            float2 v = cp2[q];
            IIR_STEP(v.y, y1);                // higher address first
            IIR_STEP(v.x, y0);
            cp2[q] = make_float2(y0, y1);
        }
    }
    __syncthreads();

    // ---- Store core ∩ [PADL, TP-PADL) (coalesced) ----
    const int wlo = max(core0, PADL);
    const int whi = min(core1, TP - PADL);
    for (int p = wlo + tid; p < whi; p += NTHR) {
        outr[p - PADL] = xsp[p - e0];
    }
}

extern "C" void kernel_launch(void* const* d_in, const int* in_sizes, int n_in,
                              void* d_out, int out_size) {
    const float* x = (const float*)d_in[0];
    float* out = (float*)d_out;
    cudaFuncSetAttribute(fused_filtfilt,
                         cudaFuncAttributeMaxDynamicSharedMemorySize, SMEMB);
    fused_filtfilt<<<ROWS * NSEG, NTHR, SMEMB>>>(x, out);
}

// round 11
// speedup vs baseline: 2.1775x; 1.2560x over previous
#include <cuda_runtime.h>

// filtfilt (butter(4,0.2)) over (8,64,48000) fp32 — fused smem kernel, v9.
// vs v8 (72.2us): interior segments use cp.async.bulk (UBLKCP) for BOTH the
// gmem->smem load and smem->gmem store: one elected thread issues a single
// bulk copy, removing ~200 per-thread LDG/STS/LDS/STG+ALU instructions and
// all load-phase scoreboard stalls. HALO=45 makes e0 = PADL (mod 4) so slab
// starts/sizes are 16B-aligned on both sides. Edge segments (odd-pad
// reflection) keep the scalar path. Compute unchanged: L=26 float2 chunks,
// W=40 truncated-FIR warmup (rel_err ~5e-5).

#define T_LEN  48000
#define PADL   15
#define TP     (T_LEN + 2 * PADL)   // 48030
#define ROWS   512
#define NSEG   8
#define SEGC   6004                 // 8*6004 = 48032 >= TP
#define NTHR   256
#define L      26                   // chunk per thread (even, conflict-free v2)
#define W      40                   // warmup depth (FIR truncation)
#define HALO   45                   // seam halo; e0 = core0-45 == 3 (mod 4)
#define BODY   (NTHR * L)           // 6656 >= SEGC + 2*HALO = 6094
#define SMEMN  (W + BODY + W)       // 6736 floats
#define SMEMF  (SMEMN * 4)          // 26944 B (16B multiple)
#define SMEMB  (SMEMF + 16)         // + mbarrier slot -> 8 blocks/SM

// Interior-segment constants
#define EXTL_I (SEGC + 2 * HALO)    // 6094 valid body samples
#define LVEC   6092                 // bulk-loaded elements (mult of 4)
#define LBYTES (LVEC * 4)           // 24368 B
#define SVEC   (SEGC - 4)           // 6000 bulk-stored elements
#define SBYTES (SVEC * 4)           // 24000 B

#define B0c 0.004824343357716228f
#define B1c 0.019297373430864913f
#define B2c 0.02894606014629737f
#define B3c 0.019297373430864913f
#define B4c 0.004824343357716228f
#define A1c (-2.369513007182038f)
#define A2c ( 2.3139884144006455f)
#define A3c (-1.0546654058785672f)
#define A4c ( 0.18737949236818502f)

// Impulse response h[k] of the IIR, computed at compile time.
struct HArr { float h[W]; };
__host__ __device__ constexpr HArr make_h() {
    HArr r{};
    double hd[W] = {};
    const double b[5] = {0.004824343357716228, 0.019297373430864913,
                         0.02894606014629737, 0.019297373430864913,
                         0.004824343357716228};
    const double a[4] = {-2.369513007182038, 2.3139884144006455,
                         -1.0546654058785672, 0.18737949236818502};
    for (int k = 0; k < W; ++k) {
        double v = (k < 5) ? b[k] : 0.0;
        for (int j = 0; j < 4; ++j)
            if (k - 1 - j >= 0) v -= a[j] * hd[k - 1 - j];
        hd[k] = v;
        r.h[k] = (float)v;
    }
    return r;
}

struct St { float w0, w1, w2, w3, s1, s2, s3, s4; };

// Truncated-FIR warmup over W samples in [base, base+W) (8B-aligned).
template <bool REV>
__device__ __forceinline__ St fir_warmup(const float* base) {
    constexpr HArr HCk = make_h();
    const float2* p2 = reinterpret_cast<const float2*>(base);
    St st = {0.f, 0.f, 0.f, 0.f, 0.f, 0.f, 0.f, 0.f};
#pragma unroll
    for (int q = 0; q < W / 2; ++q) {
        float2 v = p2[q];
#pragma unroll
        for (int e = 0; e < 2; ++e) {
            const int j = 2 * q + e;
            const int i = REV ? j : (W - 1 - j);
            const float val = e ? v.y : v.x;
            st.s1 = fmaf(HCk.h[i], val, st.s1);
            if (i >= 1) st.s2 = fmaf(HCk.h[i - 1], val, st.s2);
            if (i >= 2) st.s3 = fmaf(HCk.h[i - 2], val, st.s3);
            if (i >= 3) st.s4 = fmaf(HCk.h[i - 3], val, st.s4);
            if (i == 0) st.w0 = val;
            if (i == 1) st.w1 = val;
            if (i == 2) st.w2 = val;
            if (i == 3) st.w3 = val;
        }
    }
    return st;
}

#define IIR_STEP(xn, yout)                                   \
    do {                                                     \
        float f_ = B0c * (xn);                               \
        f_ = fmaf(B1c, w0_, f_);                             \
        f_ = fmaf(B2c, w1_, f_);                             \
        f_ = fmaf(B3c, w2_, f_);                             \
        f_ = fmaf(B4c, w3_, f_);                             \
        f_ = fmaf(-A2c, s2_, f_);                            \
        f_ = fmaf(-A3c, s3_, f_);                            \
        f_ = fmaf(-A4c, s4_, f_);                            \
        (yout) = fmaf(-A1c, s1_, f_);                        \
        w3_ = w2_; w2_ = w1_; w1_ = w0_; w0_ = (xn);         \
        s4_ = s3_; s3_ = s2_; s2_ = s1_; s1_ = (yout);       \
    } while (0)

#define ST_UNPACK(st)                                        \
    float w0_ = st.w0, w1_ = st.w1, w2_ = st.w2, w3_ = st.w3, \
          s1_ = st.s1, s2_ = st.s2, s3_ = st.s3, s4_ = st.s4

__device__ __forceinline__ void mbar_wait0(unsigned mbar) {
    asm volatile(
        "{\n\t.reg .pred P%=;\n"
        "LW%=:\n\t"
        "mbarrier.try_wait.parity.acquire.cta.shared::cta.b64 P%=, [%0], 0;\n\t"
        "@!P%= bra LW%=;\n\t}"
        :: "r"(mbar) : "memory");
}

__global__ void __launch_bounds__(NTHR, 8)
fused_filtfilt(const float* __restrict__ x, float* __restrict__ out) {
    extern __shared__ float smem_raw[];
    float* xsp = smem_raw + W;               // body coord 0 (8B-aligned)
    const int tid = threadIdx.x;
    const int blk = blockIdx.x;
    const int r = blk >> 3;
    const int sg = blk & 7;
    const float* __restrict__ xr = x + (size_t)r * T_LEN;
    float* __restrict__ outr = out + (size_t)r * T_LEN;

    const int core0 = sg * SEGC;
    const int core1 = min(core0 + SEGC, TP);
    const int e0 = max(0, core0 - HALO);
    const int ext_end = min(TP, core1 + HALO);
    const int ext_len = ext_end - e0;
    const bool interior = (sg != 0) && (sg != NSEG - 1);

    // ============ Load phase ============
    if (interior) {
        const unsigned mbar = (unsigned)__cvta_generic_to_shared(
            reinterpret_cast<char*>(smem_raw) + SMEMF);
        const float* src = xr + (e0 - PADL);          // 16B-aligned
        if (tid == 0)
            asm volatile("mbarrier.init.shared.b64 [%0], 1;" :: "r"(mbar) : "memory");
        // aprons + bulk tail (disjoint from the bulk region [W, W+LVEC))
        for (int i = tid; i < W; i += NTHR) smem_raw[i] = 0.f;
        if (tid < 2) xsp[LVEC + tid] = src[LVEC + tid];   // elements 6092,6093
        for (int i = W + EXTL_I + tid; i < SMEMN; i += NTHR) smem_raw[i] = 0.f;
        __syncthreads();                               // mbar init + zeros visible
        if (tid == 0) {
            const unsigned dst = (unsigned)__cvta_generic_to_shared(smem_raw + W);
            asm volatile(
                "mbarrier.arrive.expect_tx.shared.b64 _, [%0], %1;"
                :: "r"(mbar), "r"((unsigned)LBYTES) : "memory");
            asm volatile(
                "cp.async.bulk.shared::cta.global.mbarrier::complete_tx::bytes "
                "[%0], [%1], %2, [%3];"
                :: "r"(dst), "l"(src), "r"((unsigned)LBYTES), "r"(mbar) : "memory");
        }
        mbar_wait0(mbar);
    } else {
        for (int i = tid; i < SMEMN; i += NTHR) {
            int bi = i - W;
            float v = 0.f;
            if (bi >= 0 && bi < ext_len) {
                int j = e0 + bi - PADL;
                if (j < 0)           v = 2.f * xr[0]         - xr[-1 - j];
                else if (j >= T_LEN) v = 2.f * xr[T_LEN - 1] - xr[2 * T_LEN - 3 - j];
                else                 v = xr[j];
            }
            smem_raw[i] = v;
        }
        __syncthreads();
    }

    const int ps = tid * L;

    // ============ Forward pass (in place, float2) ============
    {
        St st = fir_warmup<false>(xsp + ps - W);
        ST_UNPACK(st);
        __syncthreads();                      // cross-chunk reads before writes
        float2* cp2 = reinterpret_cast<float2*>(xsp + ps);
        float y0, y1;
#pragma unroll
        for (int q = 0; q < L / 2; ++q) {
            float2 v = cp2[q];
            IIR_STEP(v.x, y0);
            IIR_STEP(v.y, y1);
            cp2[q] = make_float2(y0, y1);
        }
    }
    __syncthreads();

    // ---- Re-zero beyond valid extent (exact zero-init at padded row end) ----
    for (int i = ext_len + tid; i < BODY; i += NTHR) xsp[i] = 0.f;
    __syncthreads();

    // ============ Backward pass (in place, reversed, float2) ============
    {
        St st = fir_warmup<true>(xsp + ps + L);
        ST_UNPACK(st);
        __syncthreads();
        float2* cp2 = reinterpret_cast<float2*>(xsp + ps);
        float y0, y1;
#pragma unroll
        for (int q = L / 2 - 1; q >= 0; --q) {
            float2 v = cp2[q];
            IIR_STEP(v.y, y1);                // higher address first
            IIR_STEP(v.x, y0);
            cp2[q] = make_float2(y0, y1);
        }
    }
    __syncthreads();

    // ============ Store phase ============
    if (interior) {
        // scalar edges: p = core0+{0,1,2} head, core1-1 tail
        if (tid < 3) outr[core0 - PADL + tid] = xsp[HALO + tid];
        if (tid == 3) outr[core1 - 1 - PADL] = xsp[HALO + SEGC - 1];
        if (tid == 0) {
            const unsigned srcs = (unsigned)__cvta_generic_to_shared(
                xsp + HALO + 3);                       // 16B-aligned
            float* dst = outr + (core0 + 3 - PADL);    // 16B-aligned
            asm volatile("fence.proxy.async;" ::: "memory");
            asm volatile(
                "cp.async.bulk.global.shared::cta.bulk_group [%0], [%1], %2;"
                :: "l"(dst), "r"(srcs), "r"((unsigned)SBYTES) : "memory");
            asm volatile("cp.async.bulk.commit_group;" ::: "memory");
            asm volatile("cp.async.bulk.wait_group 0;" ::: "memory");
        }
    } else {
        const int wlo = max(core0, PADL);
        const int whi = min(core1, TP - PADL);
        for (int p = wlo + tid; p < whi; p += NTHR)
            outr[p - PADL] = xsp[p - e0];
    }
}

extern "C" void kernel_launch(void* const* d_in, const int* in_sizes, int n_in,
                              void* d_out, int out_size) {
    const float* x = (const float*)d_in[0];
    float* out = (float*)d_out;
    cudaFuncSetAttribute(fused_filtfilt,
                         cudaFuncAttributeMaxDynamicSharedMemorySize, SMEMB);
    fused_filtfilt<<<ROWS * NSEG, NTHR, SMEMB>>>(x, out);
}